// round 9
// baseline (speedup 1.0000x reference)
#include <cuda_runtime.h>
#include <cuda_fp16.h>
#include <cstdint>

#define H_IN   224
#define H_OUT  220
#define C_IN   32
#define N_FILT 64
#define KS     5
#define NTAP   25
#define BATCH  16

#define TR 16              // output rows per CTA (2 per warp)
#define TC 32
#define HR 20
#define HC 36
#define NLINES (HR * HC)   // 720
#define NTX 7
#define NTY 14

// A halo: [line][32ch fp16] = 64B data, 80B stride
#define ASTRIDE 80
#define A_BYTES (NLINES * ASTRIDE)          // 57600
// B: ALL taps resident, fragment order, 4096B per tap
#define B_TILE  4096
#define B_OFF   A_BYTES
#define SMEM_BYTES (B_OFF + NTAP * B_TILE)  // 160000

__device__ __half g_wf[NTAP * 2048];

// ---------------- helpers ----------------
__device__ __forceinline__ uint32_t smem_u32(const void* p) {
    uint32_t a;
    asm("{ .reg .u64 t; cvta.to.shared.u64 t, %1; cvt.u32.u64 %0, t; }" : "=r"(a) : "l"(p));
    return a;
}
__device__ __forceinline__ void cpa16(uint32_t s, const void* g) {
    asm volatile("cp.async.ca.shared.global [%0], [%1], 16;" :: "r"(s), "l"(g));
}
__device__ __forceinline__ void cp_commit() { asm volatile("cp.async.commit_group;"); }
__device__ __forceinline__ void cp_wait0()  { asm volatile("cp.async.wait_group 0;"); }

__device__ __forceinline__ void ldsm4(uint32_t* r, uint32_t a) {
    asm volatile("ldmatrix.sync.aligned.m8n8.x4.shared.b16 {%0,%1,%2,%3}, [%4];"
                 : "=r"(r[0]), "=r"(r[1]), "=r"(r[2]), "=r"(r[3]) : "r"(a));
}
__device__ __forceinline__ void ldsv4(uint32_t* r, uint32_t a) {
    asm volatile("ld.shared.v4.u32 {%0,%1,%2,%3}, [%4];"
                 : "=r"(r[0]), "=r"(r[1]), "=r"(r[2]), "=r"(r[3]) : "r"(a));
}
__device__ __forceinline__ void mma16816(float* d, const uint32_t* a,
                                         uint32_t b0, uint32_t b1) {
    asm volatile(
        "mma.sync.aligned.m16n8k16.row.col.f32.f16.f16.f32 "
        "{%0,%1,%2,%3}, {%4,%5,%6,%7}, {%8,%9}, {%0,%1,%2,%3};"
        : "+f"(d[0]), "+f"(d[1]), "+f"(d[2]), "+f"(d[3])
        : "r"(a[0]), "r"(a[1]), "r"(a[2]), "r"(a[3]), "r"(b0), "r"(b1));
}
__device__ __forceinline__ void sts16(uint32_t a, unsigned short v) {
    asm volatile("st.shared.u16 [%0], %1;" :: "r"(a), "h"(v));
}

// ---------------- prep: weights -> fp16 in mma-fragment order ----------------
__global__ void prep_weights(const float* __restrict__ w) {
    int idx = blockIdx.x * blockDim.x + threadIdx.x;
    if (idx >= NTAP * 1024) return;
    int tap = idx >> 10;
    int rem = idx & 1023;
    int grp  = rem >> 7;
    int lane = (rem >> 2) & 31;
    int r    = rem & 3;
    int ks = grp >> 2, np = grp & 3;
    int c = ks * 16 + (lane & 3) * 2 + ((r & 1) ? 8 : 0);
    int f = np * 16 + (lane >> 2)   + ((r & 2) ? 8 : 0);
    __half h0 = __float2half(w[(f * C_IN + c    ) * (KS * KS) + tap]);
    __half h1 = __float2half(w[(f * C_IN + c + 1) * (KS * KS) + tap]);
    __half2* dst = reinterpret_cast<__half2*>(g_wf + (size_t)tap * 2048);
    dst[rem] = __halves2half2(h0, h1);
}

// ---------------- main kernel ----------------
__global__ __launch_bounds__(256, 1)
void conv_mma_kernel(const float* __restrict__ x,
                     const float* __restrict__ bias,
                     float* __restrict__ out)
{
    extern __shared__ __align__(128) char smem[];
    const uint32_t sb = smem_u32(smem);

    const int tid = threadIdx.x;
    const int wid = tid >> 5, lid = tid & 31;
    const int g = lid >> 2, c4 = lid & 3;

    const int x0 = blockIdx.x * TC;
    const int y0 = blockIdx.y * TR;
    const int b  = blockIdx.z;

    // ---- stage ALL B tiles (100KB, async) ----
    #pragma unroll
    for (int j = 0; j < 25; ++j)
        cpa16(sb + B_OFF + (tid + j * 256) * 16, g_wf + ((size_t)tid + j * 256) * 8);
    cp_commit();

    // ---- build A halo (divisions hoisted out of channel loop) ----
    {
        const float* xb = x + (size_t)b * C_IN * H_IN * H_IN;
        #pragma unroll
        for (int j = 0; j < 3; ++j) {
            int line = tid + j * 256;
            if (line < NLINES) {
                int hy = line / HC, hx = line - hy * HC;
                int gy = y0 + hy, gx = x0 + hx;
                const bool ok = (gy < H_IN) && (gx < H_IN);
                const float* src = xb + (size_t)gy * H_IN + gx;
                uint32_t dst = sb + line * ASTRIDE;
                #pragma unroll
                for (int c = 0; c < C_IN; ++c) {
                    float v = ok ? src[(size_t)c * H_IN * H_IN] : 0.0f;
                    sts16(dst + c * 2, __half_as_ushort(__float2half(v)));
                }
            }
        }
    }
    cp_wait0();
    __syncthreads();      // the ONLY barrier

    // acc[mb][ns][4] : mb = (row<<1)|xhalf, warp rows {2*wid, 2*wid+1}
    float acc[4][8][4];
    #pragma unroll
    for (int mb = 0; mb < 4; ++mb)
        #pragma unroll
        for (int ns = 0; ns < 8; ++ns)
            #pragma unroll
            for (int q = 0; q < 4; ++q) acc[mb][ns][q] = 0.0f;

    const int lrow = lid & 15;
    const int lcol = lid >> 4;
    // base addr for (row, xhalf) at tap (0,0)
    const uint32_t a_base = sb + (uint32_t)((2 * wid * HC + lrow) * ASTRIDE) + lcol * 16;
    const uint32_t b_base0 = sb + B_OFF + lid * 16;

    #pragma unroll
    for (int kh = 0; kh < 5; ++kh) {
        #pragma unroll
        for (int kw = 0; kw < 5; ++kw) {
            const int tap = kh * 5 + kw;
            const uint32_t a_t = a_base + (uint32_t)((kh * HC + kw) * ASTRIDE);
            const uint32_t b_t = b_base0 + tap * B_TILE;

            #pragma unroll
            for (int kk = 0; kk < 2; ++kk) {
                // MLP batch: 4 A ldmatrix + 4 B v4 loads
                uint32_t afr[4][4];
                ldsm4(afr[0], a_t + kk * 32);                              // row0 x0-15
                ldsm4(afr[1], a_t + 16 * ASTRIDE + kk * 32);               // row0 x16-31
                ldsm4(afr[2], a_t + HC * ASTRIDE + kk * 32);               // row1 x0-15
                ldsm4(afr[3], a_t + (HC + 16) * ASTRIDE + kk * 32);        // row1 x16-31
                uint32_t bq[4][4];
                #pragma unroll
                for (int np = 0; np < 4; ++np)
                    ldsv4(bq[np], b_t + (kk * 4 + np) * 512);

                #pragma unroll
                for (int np = 0; np < 4; ++np) {
                    #pragma unroll
                    for (int mb = 0; mb < 4; ++mb) {
                        mma16816(acc[mb][2 * np + 0], afr[mb], bq[np][0], bq[np][1]);
                        mma16816(acc[mb][2 * np + 1], afr[mb], bq[np][2], bq[np][3]);
                    }
                }
            }
        }
    }

    // ---- epilogue ----
    float bv[8][2];
    #pragma unroll
    for (int ns = 0; ns < 8; ++ns) {
        bv[ns][0] = bias[ns * 8 + 2 * c4];
        bv[ns][1] = bias[ns * 8 + 2 * c4 + 1];
    }

    #pragma unroll
    for (int mb = 0; mb < 4; ++mb) {
        const int oy = y0 + 2 * wid + (mb >> 1);
        if (oy >= H_OUT) continue;
        #pragma unroll
        for (int h = 0; h < 2; ++h) {
            const int ox = x0 + (mb & 1) * 16 + h * 8 + g;
            if (ox >= H_OUT) continue;
            size_t base = (((size_t)b * N_FILT) * H_OUT + oy) * H_OUT + ox;
            #pragma unroll
            for (int ns = 0; ns < 8; ++ns) {
                int f = ns * 8 + 2 * c4;
                out[base + (size_t)f * H_OUT * H_OUT] =
                    acc[mb][ns][2 * h + 0] + bv[ns][0];
                out[base + (size_t)(f + 1) * H_OUT * H_OUT] =
                    acc[mb][ns][2 * h + 1] + bv[ns][1];
            }
        }
    }
}

extern "C" void kernel_launch(void* const* d_in, const int* in_sizes, int n_in,
                              void* d_out, int out_size) {
    const float* x    = (const float*)d_in[0];
    const float* w    = (const float*)d_in[1];
    const float* bias = (const float*)d_in[2];
    float* out = (float*)d_out;

    cudaFuncSetAttribute(conv_mma_kernel,
                         cudaFuncAttributeMaxDynamicSharedMemorySize, SMEM_BYTES);

    prep_weights<<<(NTAP * 1024 + 255) / 256, 256>>>(w);

    dim3 grid(NTX, NTY, BATCH);
    conv_mma_kernel<<<grid, 256, SMEM_BYTES>>>(x, bias, out);
}

// round 10
// speedup vs baseline: 1.0099x; 1.0099x over previous
#include <cuda_runtime.h>
#include <cuda_fp16.h>
#include <cstdint>

#define H_IN   224
#define H_OUT  220
#define C_IN   32
#define N_FILT 64
#define KS     5
#define NTAP   25
#define BATCH  16

#define TR 16              // output rows per CTA (2 per warp)
#define TC 32
#define HR 20
#define HC 36
#define NLINES (HR * HC)   // 720
#define NTX 7
#define NTY 14

#define ASTRIDE 80
#define A_BYTES (NLINES * ASTRIDE)          // 57600
#define B_TILE  4096
#define B_OFF   A_BYTES
#define SMEM_BYTES (B_OFF + NTAP * B_TILE)  // 160000

__device__ __half g_wf[NTAP * 2048];

// ---------------- helpers ----------------
__device__ __forceinline__ uint32_t smem_u32(const void* p) {
    uint32_t a;
    asm("{ .reg .u64 t; cvta.to.shared.u64 t, %1; cvt.u32.u64 %0, t; }" : "=r"(a) : "l"(p));
    return a;
}
__device__ __forceinline__ void cpa16(uint32_t s, const void* g) {
    asm volatile("cp.async.ca.shared.global [%0], [%1], 16;" :: "r"(s), "l"(g));
}
__device__ __forceinline__ void cp_commit() { asm volatile("cp.async.commit_group;"); }
__device__ __forceinline__ void cp_wait0()  { asm volatile("cp.async.wait_group 0;"); }

__device__ __forceinline__ void ldsm4(uint32_t* r, uint32_t a) {
    asm volatile("ldmatrix.sync.aligned.m8n8.x4.shared.b16 {%0,%1,%2,%3}, [%4];"
                 : "=r"(r[0]), "=r"(r[1]), "=r"(r[2]), "=r"(r[3]) : "r"(a));
}
__device__ __forceinline__ void ldsv4(uint32_t* r, uint32_t a) {
    asm volatile("ld.shared.v4.u32 {%0,%1,%2,%3}, [%4];"
                 : "=r"(r[0]), "=r"(r[1]), "=r"(r[2]), "=r"(r[3]) : "r"(a));
}
__device__ __forceinline__ void mma16816(float* d, const uint32_t* a,
                                         uint32_t b0, uint32_t b1) {
    asm volatile(
        "mma.sync.aligned.m16n8k16.row.col.f32.f16.f16.f32 "
        "{%0,%1,%2,%3}, {%4,%5,%6,%7}, {%8,%9}, {%0,%1,%2,%3};"
        : "+f"(d[0]), "+f"(d[1]), "+f"(d[2]), "+f"(d[3])
        : "r"(a[0]), "r"(a[1]), "r"(a[2]), "r"(a[3]), "r"(b0), "r"(b1));
}
__device__ __forceinline__ void sts16(uint32_t a, unsigned short v) {
    asm volatile("st.shared.u16 [%0], %1;" :: "r"(a), "h"(v));
}

// ---------------- prep: weights -> fp16 in mma-fragment order ----------------
__global__ void prep_weights(const float* __restrict__ w) {
    int idx = blockIdx.x * blockDim.x + threadIdx.x;
    if (idx >= NTAP * 1024) return;
    int tap = idx >> 10;
    int rem = idx & 1023;
    int grp  = rem >> 7;
    int lane = (rem >> 2) & 31;
    int r    = rem & 3;
    int ks = grp >> 2, np = grp & 3;
    int c = ks * 16 + (lane & 3) * 2 + ((r & 1) ? 8 : 0);
    int f = np * 16 + (lane >> 2)   + ((r & 2) ? 8 : 0);
    __half h0 = __float2half(w[(f * C_IN + c    ) * (KS * KS) + tap]);
    __half h1 = __float2half(w[(f * C_IN + c + 1) * (KS * KS) + tap]);
    __half2* dst = reinterpret_cast<__half2*>(g_wf + (size_t)tap * 2048);
    dst[rem] = __halves2half2(h0, h1);
}

// ---------------- main kernel ----------------
__global__ __launch_bounds__(256, 1)
void conv_mma_kernel(const float* __restrict__ x,
                     const float* __restrict__ bias,
                     float* __restrict__ out)
{
    extern __shared__ __align__(128) char smem[];
    const uint32_t sb = smem_u32(smem);

    const int tid = threadIdx.x;
    const int wid = tid >> 5, lid = tid & 31;
    const int g = lid >> 2, c4 = lid & 3;

    const int x0 = blockIdx.x * TC;
    const int y0 = blockIdx.y * TR;
    const int b  = blockIdx.z;

    // ---- stage ALL B tiles (100KB, async) ----
    #pragma unroll
    for (int j = 0; j < 25; ++j)
        cpa16(sb + B_OFF + (tid + j * 256) * 16, g_wf + ((size_t)tid + j * 256) * 8);
    cp_commit();

    // ---- build A halo ----
    {
        const float* xb = x + (size_t)b * C_IN * H_IN * H_IN;
        #pragma unroll
        for (int j = 0; j < 3; ++j) {
            int line = tid + j * 256;
            if (line < NLINES) {
                int hy = line / HC, hx = line - hy * HC;
                int gy = y0 + hy, gx = x0 + hx;
                const bool ok = (gy < H_IN) && (gx < H_IN);
                const float* src = xb + (size_t)gy * H_IN + gx;
                uint32_t dst = sb + line * ASTRIDE;
                #pragma unroll
                for (int c = 0; c < C_IN; ++c) {
                    float v = ok ? src[(size_t)c * H_IN * H_IN] : 0.0f;
                    sts16(dst + c * 2, __half_as_ushort(__float2half(v)));
                }
            }
        }
    }
    cp_wait0();
    __syncthreads();      // the ONLY barrier

    float acc[4][8][4];
    #pragma unroll
    for (int mb = 0; mb < 4; ++mb)
        #pragma unroll
        for (int ns = 0; ns < 8; ++ns)
            #pragma unroll
            for (int q = 0; q < 4; ++q) acc[mb][ns][q] = 0.0f;

    const int lrow = lid & 15;
    const int lcol = lid >> 4;
    const uint32_t a_base = sb + (uint32_t)((2 * wid * HC + lrow) * ASTRIDE) + lcol * 16;
    const uint32_t b_base0 = sb + B_OFF + lid * 16;

    // per-warp tap rotation: desynchronize load/mma phases across warps
    const int start = wid * 3;           // 0,3,...,21

    #pragma unroll 1
    for (int t = 0; t < NTAP; ++t) {
        int tap = t + start;
        if (tap >= NTAP) tap -= NTAP;
        const int kh = (tap * 52) >> 8;        // tap/5 for tap<25
        const int kw = tap - kh * 5;
        const uint32_t a_t = a_base + (uint32_t)((kh * HC + kw) * ASTRIDE);
        const uint32_t b_t = b_base0 + (uint32_t)tap * B_TILE;

        // whole-tap load batch: 8 ldsm + 8 ldsv4, then 64 mma
        uint32_t afr[2][4][4];                 // [kk][mb][4]
        uint32_t bq[2][4][4];                  // [kk][np][4]
        #pragma unroll
        for (int kk = 0; kk < 2; ++kk) {
            ldsm4(afr[kk][0], a_t + kk * 32);
            ldsm4(afr[kk][1], a_t + 16 * ASTRIDE + kk * 32);
            ldsm4(afr[kk][2], a_t + HC * ASTRIDE + kk * 32);
            ldsm4(afr[kk][3], a_t + (HC + 16) * ASTRIDE + kk * 32);
        }
        #pragma unroll
        for (int kk = 0; kk < 2; ++kk)
            #pragma unroll
            for (int np = 0; np < 4; ++np)
                ldsv4(bq[kk][np], b_t + (kk * 4 + np) * 512);

        #pragma unroll
        for (int kk = 0; kk < 2; ++kk) {
            #pragma unroll
            for (int np = 0; np < 4; ++np) {
                #pragma unroll
                for (int mb = 0; mb < 4; ++mb) {
                    mma16816(acc[mb][2 * np + 0], afr[kk][mb], bq[kk][np][0], bq[kk][np][1]);
                    mma16816(acc[mb][2 * np + 1], afr[kk][mb], bq[kk][np][2], bq[kk][np][3]);
                }
            }
        }
    }

    // ---- epilogue ----
    float bv[8][2];
    #pragma unroll
    for (int ns = 0; ns < 8; ++ns) {
        bv[ns][0] = bias[ns * 8 + 2 * c4];
        bv[ns][1] = bias[ns * 8 + 2 * c4 + 1];
    }

    #pragma unroll
    for (int mb = 0; mb < 4; ++mb) {
        const int oy = y0 + 2 * wid + (mb >> 1);
        if (oy >= H_OUT) continue;
        #pragma unroll
        for (int h = 0; h < 2; ++h) {
            const int ox = x0 + (mb & 1) * 16 + h * 8 + g;
            if (ox >= H_OUT) continue;
            size_t base = (((size_t)b * N_FILT) * H_OUT + oy) * H_OUT + ox;
            #pragma unroll
            for (int ns = 0; ns < 8; ++ns) {
                int f = ns * 8 + 2 * c4;
                out[base + (size_t)f * H_OUT * H_OUT] =
                    acc[mb][ns][2 * h + 0] + bv[ns][0];
                out[base + (size_t)(f + 1) * H_OUT * H_OUT] =
                    acc[mb][ns][2 * h + 1] + bv[ns][1];
            }
        }
    }
}

extern "C" void kernel_launch(void* const* d_in, const int* in_sizes, int n_in,
                              void* d_out, int out_size) {
    const float* x    = (const float*)d_in[0];
    const float* w    = (const float*)d_in[1];
    const float* bias = (const float*)d_in[2];
    float* out = (float*)d_out;

    cudaFuncSetAttribute(conv_mma_kernel,
                         cudaFuncAttributeMaxDynamicSharedMemorySize, SMEM_BYTES);

    prep_weights<<<(NTAP * 1024 + 255) / 256, 256>>>(w);

    dim3 grid(NTX, NTY, BATCH);
    conv_mma_kernel<<<grid, 256, SMEM_BYTES>>>(x, bias, out);
}